// round 1
// baseline (speedup 1.0000x reference)
#include <cuda_runtime.h>
#include <cuda_bf16.h>
#include <math.h>

// ---------------- model constants ----------------
#define VOCAB   64
#define DM      512         // D_MODEL
#define NS      32          // N_STATE
#define NH      16          // H_HEADS
#define NL      4           // LAYERS
#define DIN     1024        // D_INNER
#define PH      64          // P_HEAD
#define CONV    1088        // CONV_DIM
#define KC      4
#define DPROJ   2128        // D_IN_PROJ
#define BB      4           // BATCH
#define SS      1024        // SEQ
#define TT      (BB*SS)     // 4096 rows
#define EPSV    1e-5f

// ---------------- scratch (static device allocation; no cudaMalloc) ----------
// offsets in floats
#define OFF_H    0u
#define OFF_U    (OFF_H  + TT*DM)        // 2,097,152
#define OFF_ZX   (OFF_U  + TT*DM)
#define OFF_XC   (OFF_ZX + TT*DPROJ)
#define OFF_B    (OFF_XC + TT*DIN)
#define OFF_C    (OFF_B  + TT*NS)
#define OFF_DT   (OFF_C  + TT*NS)
#define OFF_DA   (OFF_DT + TT*NH)
#define OFF_Y    (OFF_DA + TT*NH)
#define OFF_G    (OFF_Y  + TT*DIN)
#define SCRATCH_TOTAL (OFF_G + TT*DIN)

__device__ float g_scratch[SCRATCH_TOTAL];

// ---------------- embedding gather ----------------
__global__ void embed_kernel(const int* __restrict__ tok,
                             const float* __restrict__ emb,
                             float* __restrict__ h) {
    for (int i = blockIdx.x * blockDim.x + threadIdx.x; i < TT * DM;
         i += gridDim.x * blockDim.x) {
        int row = i >> 9;          // /DM
        int d   = i & (DM - 1);
        h[i] = emb[tok[row] * DM + d];
    }
}

// ---------------- rmsnorm over D_MODEL=512, one block per row --------------
__global__ void rmsnorm_kernel(const float* __restrict__ x,
                               const float* __restrict__ w,
                               float* __restrict__ u) {
    int row = blockIdx.x;
    const float* xr = x + (size_t)row * DM;
    int t = threadIdx.x;                 // 256 threads
    float v0 = xr[t], v1 = xr[t + 256];
    float ss = v0 * v0 + v1 * v1;
    #pragma unroll
    for (int o = 16; o; o >>= 1) ss += __shfl_down_sync(0xffffffffu, ss, o);
    __shared__ float red[8];
    if ((t & 31) == 0) red[t >> 5] = ss;
    __syncthreads();
    if (t < 8) {
        float r = red[t];
        #pragma unroll
        for (int o = 4; o; o >>= 1) r += __shfl_down_sync(0xffu, r, o);
        if (t == 0) red[0] = r;
    }
    __syncthreads();
    float scale = rsqrtf(red[0] * (1.0f / DM) + EPSV);
    u[(size_t)row * DM + t]       = v0 * scale * w[t];
    u[(size_t)row * DM + t + 256] = v1 * scale * w[t + 256];
}

// ---------------- SGEMM: C[M,N] = A[M,K] @ B[K,N] + bias[N] (+res[M,N]) -----
// M % 64 == 0, K % 16 == 0, N % 4 == 0 (N guarded at tile edge)
#define BM 64
#define BN 64
#define BK 16
__global__ void __launch_bounds__(256)
sgemm_kernel(const float* __restrict__ A, const float* __restrict__ B,
             const float* __restrict__ bias, const float* __restrict__ res,
             float* __restrict__ C, int M, int N, int K) {
    __shared__ float As[BK][BM + 1];
    __shared__ float Bs[BK][BN];
    int tid = threadIdx.x;
    int bm = blockIdx.y * BM;
    int bn = blockIdx.x * BN;
    int tx = tid & 15, ty = tid >> 4;

    int ar = tid >> 2, ac = (tid & 3) * 4;     // A tile load: 64x16
    int br = tid >> 4, bc = (tid & 15) * 4;    // B tile load: 16x64

    float acc[4][4];
    #pragma unroll
    for (int i = 0; i < 4; i++)
        #pragma unroll
        for (int j = 0; j < 4; j++) acc[i][j] = 0.0f;

    for (int k0 = 0; k0 < K; k0 += BK) {
        float4 a4 = *reinterpret_cast<const float4*>(
            &A[(size_t)(bm + ar) * K + k0 + ac]);
        As[ac + 0][ar] = a4.x;
        As[ac + 1][ar] = a4.y;
        As[ac + 2][ar] = a4.z;
        As[ac + 3][ar] = a4.w;

        int gn = bn + bc;
        const float* Brow = &B[(size_t)(k0 + br) * N];
        float4 b4;
        if (gn + 3 < N) {
            b4 = *reinterpret_cast<const float4*>(&Brow[gn]);
        } else {
            b4.x = (gn + 0 < N) ? Brow[gn + 0] : 0.0f;
            b4.y = (gn + 1 < N) ? Brow[gn + 1] : 0.0f;
            b4.z = (gn + 2 < N) ? Brow[gn + 2] : 0.0f;
            b4.w = (gn + 3 < N) ? Brow[gn + 3] : 0.0f;
        }
        *reinterpret_cast<float4*>(&Bs[br][bc]) = b4;
        __syncthreads();

        #pragma unroll
        for (int kk = 0; kk < BK; kk++) {
            float a0 = As[kk][ty * 4 + 0];
            float a1 = As[kk][ty * 4 + 1];
            float a2 = As[kk][ty * 4 + 2];
            float a3 = As[kk][ty * 4 + 3];
            float4 bv = reinterpret_cast<float4*>(&Bs[kk][0])[tx];
            acc[0][0] += a0 * bv.x; acc[0][1] += a0 * bv.y;
            acc[0][2] += a0 * bv.z; acc[0][3] += a0 * bv.w;
            acc[1][0] += a1 * bv.x; acc[1][1] += a1 * bv.y;
            acc[1][2] += a1 * bv.z; acc[1][3] += a1 * bv.w;
            acc[2][0] += a2 * bv.x; acc[2][1] += a2 * bv.y;
            acc[2][2] += a2 * bv.z; acc[2][3] += a2 * bv.w;
            acc[3][0] += a3 * bv.x; acc[3][1] += a3 * bv.y;
            acc[3][2] += a3 * bv.z; acc[3][3] += a3 * bv.w;
        }
        __syncthreads();
    }

    #pragma unroll
    for (int i = 0; i < 4; i++) {
        int row = bm + ty * 4 + i;
        #pragma unroll
        for (int j = 0; j < 4; j++) {
            int col = bn + tx * 4 + j;
            if (col < N) {
                float v = acc[i][j] + bias[col];
                if (res) v += res[(size_t)row * N + col];
                C[(size_t)row * N + col] = v;
            }
        }
    }
}

// ---------------- causal depthwise conv + silu + split, plus dt/dA ----------
__global__ void conv_dt_kernel(const float* __restrict__ zx,
                               const float* __restrict__ cw,
                               const float* __restrict__ cb,
                               const float* __restrict__ dtb,
                               const float* __restrict__ Alog,
                               float* __restrict__ xc,
                               float* __restrict__ Bm,
                               float* __restrict__ Cm,
                               float* __restrict__ dtO,
                               float* __restrict__ dAO) {
    int row = blockIdx.x;              // 0..TT-1
    int b = row >> 10;                 // /SS
    int t = row & (SS - 1);
    for (int c = threadIdx.x; c < CONV; c += blockDim.x) {
        float acc = cb[c];
        #pragma unroll
        for (int k = 0; k < KC; k++) {
            int tt = t + k - (KC - 1);
            if (tt >= 0)
                acc += zx[(size_t)(b * SS + tt) * DPROJ + DIN + c] * cw[c * KC + k];
        }
        float s = acc / (1.0f + expf(-acc));   // silu
        if (c < DIN)            xc[(size_t)row * DIN + c] = s;
        else if (c < DIN + NS)  Bm[(size_t)row * NS + (c - DIN)] = s;
        else                    Cm[(size_t)row * NS + (c - DIN - NS)] = s;
    }
    if (threadIdx.x < NH) {
        int hh = threadIdx.x;
        float v = zx[(size_t)row * DPROJ + DIN + CONV + hh] + dtb[hh];
        float sp = (v > 20.0f) ? v : log1pf(expf(v));
        dtO[row * NH + hh] = sp;
        dAO[row * NH + hh] = expf(sp * (-expf(Alog[hh])));
    }
}

// ---------------- SSD sequential scan -----------------------------------
// grid: BB*NH*4 = 256 blocks (4 p-chunks of 16 per head); block: 128 threads.
// thread = (pl in 0..15, ns in 0..7); each thread owns n = ns*4 .. ns*4+3.
#define SCAN_TS 16
__global__ void __launch_bounds__(128)
scan_kernel(const float* __restrict__ xc, const float* __restrict__ Bm,
            const float* __restrict__ Cm, const float* __restrict__ dt,
            const float* __restrict__ dA, const float* __restrict__ Dp,
            float* __restrict__ y) {
    int blk = blockIdx.x;
    int pch = blk & 3;
    int bh  = blk >> 2;
    int b   = bh >> 4;
    int hh  = bh & 15;
    int tid = threadIdx.x;
    int pl  = tid >> 3;
    int ns  = tid & 7;
    int p   = pch * 16 + pl;

    __shared__ float4 sB[SCAN_TS][8];
    __shared__ float4 sC[SCAN_TS][8];
    __shared__ float  sx[SCAN_TS][16];
    __shared__ float  sdA[SCAN_TS];
    __shared__ float  sdt[SCAN_TS];

    float h0 = 0.f, h1 = 0.f, h2 = 0.f, h3 = 0.f;
    float dparam = Dp[hh];
    int rowbase = b * SS;

    for (int t0 = 0; t0 < SS; t0 += SCAN_TS) {
        {   // exactly one float4 of B and C per thread (16*8 == 128)
            int ts = tid >> 3, nf = tid & 7;
            int row = rowbase + t0 + ts;
            sB[ts][nf] = reinterpret_cast<const float4*>(&Bm[(size_t)row * NS])[nf];
            sC[ts][nf] = reinterpret_cast<const float4*>(&Cm[(size_t)row * NS])[nf];
        }
        for (int i = tid; i < SCAN_TS * 16; i += 128) {
            int ts = i >> 4, ppl = i & 15;
            int row = rowbase + t0 + ts;
            sx[ts][ppl] = xc[(size_t)row * DIN + hh * PH + pch * 16 + ppl];
        }
        if (tid < SCAN_TS) {
            int row = rowbase + t0 + tid;
            sdA[tid] = dA[row * NH + hh];
            sdt[tid] = dt[row * NH + hh];
        }
        __syncthreads();

        #pragma unroll 4
        for (int ts = 0; ts < SCAN_TS; ts++) {
            float a    = sdA[ts];
            float xval = sx[ts][pl];
            float dtx  = sdt[ts] * xval;
            float4 Bv = sB[ts][ns];
            float4 Cv = sC[ts][ns];
            h0 = fmaf(a, h0, dtx * Bv.x);
            h1 = fmaf(a, h1, dtx * Bv.y);
            h2 = fmaf(a, h2, dtx * Bv.z);
            h3 = fmaf(a, h3, dtx * Bv.w);
            float acc = h0 * Cv.x;
            acc = fmaf(h1, Cv.y, acc);
            acc = fmaf(h2, Cv.z, acc);
            acc = fmaf(h3, Cv.w, acc);
            acc += __shfl_down_sync(0xffffffffu, acc, 4, 8);
            acc += __shfl_down_sync(0xffffffffu, acc, 2, 8);
            acc += __shfl_down_sync(0xffffffffu, acc, 1, 8);
            if (ns == 0) {
                int row = rowbase + t0 + ts;
                y[(size_t)row * DIN + hh * PH + p] = fmaf(xval, dparam, acc);
            }
        }
        __syncthreads();
    }
}

// ---------------- gate (y * silu(z)) + rmsnorm over D_INNER -----------------
__global__ void gate_norm_kernel(const float* __restrict__ y,
                                 const float* __restrict__ zx,
                                 const float* __restrict__ gw,
                                 float* __restrict__ g) {
    int row = blockIdx.x;
    __shared__ float sv[DIN];
    __shared__ float red[8];
    float ss = 0.0f;
    for (int c = threadIdx.x; c < DIN; c += blockDim.x) {   // 256 thr, 4 iters
        float z = zx[(size_t)row * DPROJ + c];
        float v = y[(size_t)row * DIN + c] * (z / (1.0f + expf(-z)));
        sv[c] = v;
        ss += v * v;
    }
    #pragma unroll
    for (int o = 16; o; o >>= 1) ss += __shfl_down_sync(0xffffffffu, ss, o);
    if ((threadIdx.x & 31) == 0) red[threadIdx.x >> 5] = ss;
    __syncthreads();
    if (threadIdx.x < 8) {
        float r = red[threadIdx.x];
        #pragma unroll
        for (int o = 4; o; o >>= 1) r += __shfl_down_sync(0xffu, r, o);
        if (threadIdx.x == 0) red[0] = r;
    }
    __syncthreads();
    float scale = rsqrtf(red[0] * (1.0f / DIN) + EPSV);
    for (int c = threadIdx.x; c < DIN; c += blockDim.x)
        g[(size_t)row * DIN + c] = sv[c] * scale * gw[c];
}

// ---------------- launch ----------------
extern "C" void kernel_launch(void* const* d_in, const int* in_sizes, int n_in,
                              void* d_out, int out_size) {
    const int*   tok     = (const int*)  d_in[0];
    const float* emb     = (const float*)d_in[1];
    const float* norm_w  = (const float*)d_in[2];
    const float* W_in    = (const float*)d_in[3];
    const float* b_in    = (const float*)d_in[4];
    const float* conv_w  = (const float*)d_in[5];
    const float* conv_b  = (const float*)d_in[6];
    const float* dt_bias = (const float*)d_in[7];
    const float* A_log   = (const float*)d_in[8];
    const float* D_param = (const float*)d_in[9];
    const float* gnorm_w = (const float*)d_in[10];
    const float* W_out   = (const float*)d_in[11];
    const float* b_out   = (const float*)d_in[12];
    const float* head_w  = (const float*)d_in[13];
    const float* head_b  = (const float*)d_in[14];

    float* scratch = nullptr;
    cudaGetSymbolAddress((void**)&scratch, g_scratch);
    float* gh  = scratch + OFF_H;
    float* gu  = scratch + OFF_U;
    float* gzx = scratch + OFF_ZX;
    float* gxc = scratch + OFF_XC;
    float* gB  = scratch + OFF_B;
    float* gC  = scratch + OFF_C;
    float* gdt = scratch + OFF_DT;
    float* gdA = scratch + OFF_DA;
    float* gy  = scratch + OFF_Y;
    float* gg  = scratch + OFF_G;

    embed_kernel<<<2048, 256>>>(tok, emb, gh);

    for (int L = 0; L < NL; L++) {
        rmsnorm_kernel<<<TT, 256>>>(gh, norm_w + L * DM, gu);
        sgemm_kernel<<<dim3((DPROJ + BN - 1) / BN, TT / BM), 256>>>(
            gu, W_in + (size_t)L * DM * DPROJ, b_in + L * DPROJ,
            nullptr, gzx, TT, DPROJ, DM);
        conv_dt_kernel<<<TT, 128>>>(gzx, conv_w + L * CONV * KC,
                                    conv_b + L * CONV, dt_bias + L * NH,
                                    A_log + L * NH, gxc, gB, gC, gdt, gdA);
        scan_kernel<<<BB * NH * 4, 128>>>(gxc, gB, gC, gdt, gdA,
                                          D_param + L * NH, gy);
        gate_norm_kernel<<<TT, 256>>>(gy, gzx, gnorm_w + L * DIN, gg);
        sgemm_kernel<<<dim3(DM / BN, TT / BM), 256>>>(
            gg, W_out + (size_t)L * DIN * DM, b_out + L * DM,
            gh, gh, TT, DM, DIN);
    }

    sgemm_kernel<<<dim3(1, TT / BM), 256>>>(
        gh, head_w, head_b, nullptr, (float*)d_out, TT, VOCAB, DM);
}

// round 5
// speedup vs baseline: 2.6770x; 2.6770x over previous
#include <cuda_runtime.h>
#include <cuda_fp16.h>
#include <mma.h>
#include <math.h>

using namespace nvcuda;

// ---------------- model constants ----------------
#define VOCAB   64
#define DM      512
#define NS      32
#define NH      16
#define NL      4
#define DIN     1024
#define PH      64
#define CONV    1088
#define KC      4
#define DPROJ   2128
#define BB      4
#define SS      1024
#define TT      (BB*SS)
#define EPSV    1e-5f

// ---------------- fp32 scratch ----------------
#define OFF_H    0u
#define OFF_ZX   (OFF_H  + TT*DM)
#define OFF_XC   (OFF_ZX + TT*DPROJ)
#define OFF_B    (OFF_XC + TT*DIN)
#define OFF_C    (OFF_B  + TT*NS)
#define OFF_DT   (OFF_C  + TT*NS)
#define OFF_DA   (OFF_DT + TT*NH)
#define OFF_Y    (OFF_DA + TT*NH)
#define SCRATCH_TOTAL (OFF_Y + TT*DIN)
__device__ float g_scratch[SCRATCH_TOTAL];

// ---------------- fp16 hi/lo scratch ----------------
#define WIN_SZ  (NL*DM*DPROJ)
#define WOUT_SZ (NL*DIN*DM)
#define HEAD_SZ (DM*VOCAB)
#define U_SZ    (TT*DM)
#define G_SZ    (TT*DIN)

#define HO_WINH  0u
#define HO_WINL  (HO_WINH + WIN_SZ)
#define HO_WOUTH (HO_WINL + WIN_SZ)
#define HO_WOUTL (HO_WOUTH + WOUT_SZ)
#define HO_HEADH (HO_WOUTL + WOUT_SZ)
#define HO_HEADL (HO_HEADH + HEAD_SZ)
#define HO_UH    (HO_HEADL + HEAD_SZ)
#define HO_UL    (HO_UH + U_SZ)
#define HO_GH    (HO_UL + U_SZ)
#define HO_GL    (HO_GH + G_SZ)
#define HO_HH    (HO_GL + G_SZ)
#define HO_HL    (HO_HH + U_SZ)
#define HALF_TOTAL (HO_HL + U_SZ)
__device__ __half g_half[HALF_TOTAL];

// ---------------- embedding gather ----------------
__global__ void embed_kernel(const int* __restrict__ tok,
                             const float* __restrict__ emb,
                             float* __restrict__ h) {
    for (int i = blockIdx.x * blockDim.x + threadIdx.x; i < TT * DM;
         i += gridDim.x * blockDim.x) {
        int row = i >> 9;
        int d   = i & (DM - 1);
        h[i] = emb[tok[row] * DM + d];
    }
}

// ---------------- fp32 -> fp16 hi/lo split ----------------
__global__ void split_kernel(const float* __restrict__ x,
                             __half* __restrict__ hi,
                             __half* __restrict__ lo, int n) {
    for (int i = blockIdx.x * blockDim.x + threadIdx.x; i < n;
         i += gridDim.x * blockDim.x) {
        float v = x[i];
        __half p = __float2half_rn(v);
        hi[i] = p;
        lo[i] = __float2half_rn(v - __half2float(p));
    }
}

// ---------------- rmsnorm over D_MODEL=512 -> hi/lo fp16 --------------
__global__ void rmsnorm_kernel(const float* __restrict__ x,
                               const float* __restrict__ w,
                               __half* __restrict__ uhi,
                               __half* __restrict__ ulo) {
    int row = blockIdx.x;
    const float* xr = x + (size_t)row * DM;
    int t = threadIdx.x;
    float v0 = xr[t];
    float v1 = xr[t + 256];
    float ss = v0 * v0 + v1 * v1;
    #pragma unroll
    for (int o = 16; o; o >>= 1) ss += __shfl_down_sync(0xffffffffu, ss, o);
    __shared__ float red[8];
    if ((t & 31) == 0) red[t >> 5] = ss;
    __syncthreads();
    if (t < 8) {
        float r = red[t];
        #pragma unroll
        for (int o = 4; o; o >>= 1) r += __shfl_down_sync(0xffu, r, o);
        if (t == 0) red[0] = r;
    }
    __syncthreads();
    float scale = rsqrtf(red[0] * (1.0f / DM) + EPSV);
    float o0 = v0 * scale * w[t];
    float o1 = v1 * scale * w[t + 256];
    __half p0 = __float2half_rn(o0);
    __half p1 = __float2half_rn(o1);
    uhi[(size_t)row * DM + t]       = p0;
    ulo[(size_t)row * DM + t]       = __float2half_rn(o0 - __half2float(p0));
    uhi[(size_t)row * DM + t + 256] = p1;
    ulo[(size_t)row * DM + t + 256] = __float2half_rn(o1 - __half2float(p1));
}

// ---------------- fp16-split WMMA GEMM ----------------
// C[M,N] = (Ah+Al)[M,K] @ (Bh+Bl)[K,N] + bias[N] (+res)
// Block tile 128x64, k-tile 32. 256 threads = 8 warps (4x2), warp tile 32x32.
#define HBM_ 128
#define HBN_ 64
#define HBK_ 32
#define ASTR 40
#define BSTR 72
#define A_SZH (HBM_*ASTR)
#define B_SZH (HBK_*BSTR)
#define SMEM_BYTES 32768

__global__ void __launch_bounds__(256)
hgemm_kernel(const __half* __restrict__ Ah, const __half* __restrict__ Al,
             const __half* __restrict__ Bh, const __half* __restrict__ Bl,
             const float* __restrict__ bias, const float* __restrict__ res,
             float* __restrict__ C, int M, int N, int K)
{
    __shared__ __align__(16) unsigned char smem_raw[SMEM_BYTES];
    __half* sAh = (__half*)smem_raw;
    __half* sAl = sAh + A_SZH;
    __half* sBh = sAl + A_SZH;
    __half* sBl = sBh + B_SZH;
    float*  sOut = (float*)smem_raw;

    int tid = threadIdx.x;
    int bm = blockIdx.y * HBM_;
    int bn = blockIdx.x * HBN_;

    int lane = tid & 31;
    int warp = tid >> 5;
    int wm = (warp >> 1) * 32;
    int wn = (warp & 1) * 32;

    // A loads: 128x32 halves = 512 uint4 chunks per array, 2 per thread
    int a_row0 = tid >> 2;
    int a_row1 = a_row0 + 64;
    int a_col  = (tid & 3) * 8;
    // B loads: 32x64 halves = 256 chunks, 1 per thread
    int b_row = tid >> 3;
    int b_col = (tid & 7) * 8;
    bool bvalid = (bn + b_col + 8 <= N);

    wmma::fragment<wmma::accumulator, 16, 16, 16, float> acc[2][2];
    #pragma unroll
    for (int mi = 0; mi < 2; mi++) {
        #pragma unroll
        for (int ni = 0; ni < 2; ni++) {
            wmma::fill_fragment(acc[mi][ni], 0.0f);
        }
    }

    int KT = K / HBK_;
    for (int kt = 0; kt < KT; kt++) {
        int k0 = kt * HBK_;
        __syncthreads();
        // stage A hi/lo
        {
            const uint4* gA;
            gA = (const uint4*)(Ah + (size_t)(bm + a_row0) * K + k0 + a_col);
            *(uint4*)(sAh + a_row0 * ASTR + a_col) = *gA;
            gA = (const uint4*)(Ah + (size_t)(bm + a_row1) * K + k0 + a_col);
            *(uint4*)(sAh + a_row1 * ASTR + a_col) = *gA;
            gA = (const uint4*)(Al + (size_t)(bm + a_row0) * K + k0 + a_col);
            *(uint4*)(sAl + a_row0 * ASTR + a_col) = *gA;
            gA = (const uint4*)(Al + (size_t)(bm + a_row1) * K + k0 + a_col);
            *(uint4*)(sAl + a_row1 * ASTR + a_col) = *gA;
        }
        // stage B hi/lo
        if (bvalid) {
            const uint4* gB;
            gB = (const uint4*)(Bh + (size_t)(k0 + b_row) * N + bn + b_col);
            *(uint4*)(sBh + b_row * BSTR + b_col) = *gB;
            gB = (const uint4*)(Bl + (size_t)(k0 + b_row) * N + bn + b_col);
            *(uint4*)(sBl + b_row * BSTR + b_col) = *gB;
        } else {
            uint4 z;
            z.x = 0u; z.y = 0u; z.z = 0u; z.w = 0u;
            *(uint4*)(sBh + b_row * BSTR + b_col) = z;
            *(uint4*)(sBl + b_row * BSTR + b_col) = z;
        }
        __syncthreads();

        #pragma unroll
        for (int kc = 0; kc < 2; kc++) {
            wmma::fragment<wmma::matrix_a, 16, 16, 16, half, wmma::row_major> fah[2];
            wmma::fragment<wmma::matrix_a, 16, 16, 16, half, wmma::row_major> fal[2];
            wmma::fragment<wmma::matrix_b, 16, 16, 16, half, wmma::row_major> fbh[2];
            wmma::fragment<wmma::matrix_b, 16, 16, 16, half, wmma::row_major> fbl[2];
            #pragma unroll
            for (int mi = 0; mi < 2; mi++) {
                const __half* pa = sAh + (wm + mi * 16) * ASTR + kc * 16;
                wmma::load_matrix_sync(fah[mi], pa, ASTR);
                const __half* pl = sAl + (wm + mi * 16) * ASTR + kc * 16;
                wmma::load_matrix_sync(fal[mi], pl, ASTR);
            }
            #pragma unroll
            for (int ni = 0; ni < 2; ni++) {
                const __half* pb = sBh + (kc * 16) * BSTR + wn + ni * 16;
                wmma::load_matrix_sync(fbh[ni], pb, BSTR);
                const __half* pq = sBl + (kc * 16) * BSTR + wn + ni * 16;
                wmma::load_matrix_sync(fbl[ni], pq, BSTR);
            }
            #pragma unroll
            for (int mi = 0; mi < 2; mi++) {
                #pragma unroll
                for (int ni = 0; ni < 2; ni++) {
                    wmma::mma_sync(acc[mi][ni], fah[mi], fbh[ni], acc[mi][ni]);
                    wmma::mma_sync(acc[mi][ni], fah[mi], fbl[ni], acc[mi][ni]);
                    wmma::mma_sync(acc[mi][ni], fal[mi], fbh[ni], acc[mi][ni]);
                }
            }
        }
    }

    // ---- epilogue: park accumulators in smem, then guarded global stores ----
    __syncthreads();
    float* myOut = sOut + warp * 1024;
    #pragma unroll
    for (int mi = 0; mi < 2; mi++) {
        #pragma unroll
        for (int ni = 0; ni < 2; ni++) {
            wmma::store_matrix_sync(myOut + mi * 16 * 32 + ni * 16,
                                    acc[mi][ni], 32, wmma::mem_row_major);
        }
    }
    __syncwarp();
    int colg = bn + wn + lane;
    if (colg < N) {
        float bc = bias[colg];
        #pragma unroll 4
        for (int r = 0; r < 32; r++) {
            int rowg = bm + wm + r;
            float v = myOut[r * 32 + lane] + bc;
            size_t off = (size_t)rowg * N + colg;
            if (res) v += res[off];
            C[off] = v;
        }
    }
}

// ---------------- causal depthwise conv + silu + split, plus dt/dA ----------
__global__ void conv_dt_kernel(const float* __restrict__ zx,
                               const float* __restrict__ cw,
                               const float* __restrict__ cb,
                               const float* __restrict__ dtb,
                               const float* __restrict__ Alog,
                               float* __restrict__ xc,
                               float* __restrict__ Bm,
                               float* __restrict__ Cm,
                               float* __restrict__ dtO,
                               float* __restrict__ dAO) {
    int row = blockIdx.x;
    int b = row >> 10;
    int t = row & (SS - 1);
    for (int c = threadIdx.x; c < CONV; c += blockDim.x) {
        float acc = cb[c];
        #pragma unroll
        for (int k = 0; k < KC; k++) {
            int tt = t + k - (KC - 1);
            if (tt >= 0)
                acc += zx[(size_t)(b * SS + tt) * DPROJ + DIN + c] * cw[c * KC + k];
        }
        float s = acc / (1.0f + expf(-acc));
        if (c < DIN)            xc[(size_t)row * DIN + c] = s;
        else if (c < DIN + NS)  Bm[(size_t)row * NS + (c - DIN)] = s;
        else                    Cm[(size_t)row * NS + (c - DIN - NS)] = s;
    }
    if (threadIdx.x < NH) {
        int hh = threadIdx.x;
        float v = zx[(size_t)row * DPROJ + DIN + CONV + hh] + dtb[hh];
        float sp = (v > 20.0f) ? v : log1pf(expf(v));
        dtO[row * NH + hh] = sp;
        dAO[row * NH + hh] = expf(sp * (-expf(Alog[hh])));
    }
}

// ---------------- SSD sequential scan -----------------------------------
#define SCAN_TS 16
__global__ void __launch_bounds__(128)
scan_kernel(const float* __restrict__ xc, const float* __restrict__ Bm,
            const float* __restrict__ Cm, const float* __restrict__ dt,
            const float* __restrict__ dA, const float* __restrict__ Dp,
            float* __restrict__ y) {
    int blk = blockIdx.x;
    int pch = blk & 3;
    int bh  = blk >> 2;
    int b   = bh >> 4;
    int hh  = bh & 15;
    int tid = threadIdx.x;
    int pl  = tid >> 3;
    int ns  = tid & 7;
    int p   = pch * 16 + pl;

    __shared__ float4 sB[SCAN_TS][8];
    __shared__ float4 sC[SCAN_TS][8];
    __shared__ float  sx[SCAN_TS][16];
    __shared__ float  sdA[SCAN_TS];
    __shared__ float  sdt[SCAN_TS];

    float h0 = 0.f, h1 = 0.f, h2 = 0.f, h3 = 0.f;
    float dparam = Dp[hh];
    int rowbase = b * SS;

    for (int t0 = 0; t0 < SS; t0 += SCAN_TS) {
        {
            int ts = tid >> 3;
            int nf = tid & 7;
            int row = rowbase + t0 + ts;
            sB[ts][nf] = ((const float4*)(Bm + (size_t)row * NS))[nf];
            sC[ts][nf] = ((const float4*)(Cm + (size_t)row * NS))[nf];
        }
        for (int i = tid; i < SCAN_TS * 16; i += 128) {
            int ts = i >> 4;
            int ppl = i & 15;
            int row = rowbase + t0 + ts;
            sx[ts][ppl] = xc[(size_t)row * DIN + hh * PH + pch * 16 + ppl];
        }
        if (tid < SCAN_TS) {
            int row = rowbase + t0 + tid;
            sdA[tid] = dA[row * NH + hh];
            sdt[tid] = dt[row * NH + hh];
        }
        __syncthreads();

        #pragma unroll 4
        for (int ts = 0; ts < SCAN_TS; ts++) {
            float a    = sdA[ts];
            float xval = sx[ts][pl];
            float dtx  = sdt[ts] * xval;
            float4 Bv = sB[ts][ns];
            float4 Cv = sC[ts][ns];
            h0 = fmaf(a, h0, dtx * Bv.x);
            h1 = fmaf(a, h1, dtx * Bv.y);
            h2 = fmaf(a, h2, dtx * Bv.z);
            h3 = fmaf(a, h3, dtx * Bv.w);
            float acc = h0 * Cv.x;
            acc = fmaf(h1, Cv.y, acc);
            acc = fmaf(h2, Cv.z, acc);
            acc = fmaf(h3, Cv.w, acc);
            acc += __shfl_down_sync(0xffffffffu, acc, 4, 8);
            acc += __shfl_down_sync(0xffffffffu, acc, 2, 8);
            acc += __shfl_down_sync(0xffffffffu, acc, 1, 8);
            if (ns == 0) {
                int row = rowbase + t0 + ts;
                y[(size_t)row * DIN + hh * PH + p] = fmaf(xval, dparam, acc);
            }
        }
        __syncthreads();
    }
}

// ---------------- gate (y * silu(z)) + rmsnorm over D_INNER -> hi/lo --------
__global__ void gate_norm_kernel(const float* __restrict__ y,
                                 const float* __restrict__ zx,
                                 const float* __restrict__ gw,
                                 __half* __restrict__ ghi,
                                 __half* __restrict__ glo) {
    int row = blockIdx.x;
    __shared__ float sv[DIN];
    __shared__ float red[8];
    float ss = 0.0f;
    for (int c = threadIdx.x; c < DIN; c += blockDim.x) {
        float z = zx[(size_t)row * DPROJ + c];
        float v = y[(size_t)row * DIN + c] * (z / (1.0f + expf(-z)));
        sv[c] = v;
        ss += v * v;
    }
    #pragma unroll
    for (int o = 16; o; o >>= 1) ss += __shfl_down_sync(0xffffffffu, ss, o);
    if ((threadIdx.x & 31) == 0) red[threadIdx.x >> 5] = ss;
    __syncthreads();
    if (threadIdx.x < 8) {
        float r = red[threadIdx.x];
        #pragma unroll
        for (int o = 4; o; o >>= 1) r += __shfl_down_sync(0xffu, r, o);
        if (threadIdx.x == 0) red[0] = r;
    }
    __syncthreads();
    float scale = rsqrtf(red[0] * (1.0f / DIN) + EPSV);
    for (int c = threadIdx.x; c < DIN; c += blockDim.x) {
        float v = sv[c] * scale * gw[c];
        __half p = __float2half_rn(v);
        ghi[(size_t)row * DIN + c] = p;
        glo[(size_t)row * DIN + c] = __float2half_rn(v - __half2float(p));
    }
}

// ---------------- launch ----------------
extern "C" void kernel_launch(void* const* d_in, const int* in_sizes, int n_in,
                              void* d_out, int out_size) {
    const int*   tok     = (const int*)  d_in[0];
    const float* emb     = (const float*)d_in[1];
    const float* norm_w  = (const float*)d_in[2];
    const float* W_in    = (const float*)d_in[3];
    const float* b_in    = (const float*)d_in[4];
    const float* conv_w  = (const float*)d_in[5];
    const float* conv_b  = (const float*)d_in[6];
    const float* dt_bias = (const float*)d_in[7];
    const float* A_log   = (const float*)d_in[8];
    const float* D_param = (const float*)d_in[9];
    const float* gnorm_w = (const float*)d_in[10];
    const float* W_out   = (const float*)d_in[11];
    const float* b_out   = (const float*)d_in[12];
    const float* head_w  = (const float*)d_in[13];
    const float* head_b  = (const float*)d_in[14];

    float* scratch = nullptr;
    cudaGetSymbolAddress((void**)&scratch, g_scratch);
    __half* hs = nullptr;
    cudaGetSymbolAddress((void**)&hs, g_half);

    float* gh  = scratch + OFF_H;
    float* gzx = scratch + OFF_ZX;
    float* gxc = scratch + OFF_XC;
    float* gB  = scratch + OFF_B;
    float* gC  = scratch + OFF_C;
    float* gdt = scratch + OFF_DT;
    float* gdA = scratch + OFF_DA;
    float* gy  = scratch + OFF_Y;

    __half* WinH  = hs + HO_WINH;
    __half* WinL  = hs + HO_WINL;
    __half* WoutH = hs + HO_WOUTH;
    __half* WoutL = hs + HO_WOUTL;
    __half* HeadH = hs + HO_HEADH;
    __half* HeadL = hs + HO_HEADL;
    __half* UH    = hs + HO_UH;
    __half* UL    = hs + HO_UL;
    __half* GHp   = hs + HO_GH;
    __half* GLp   = hs + HO_GL;
    __half* HHp   = hs + HO_HH;
    __half* HLp   = hs + HO_HL;

    embed_kernel<<<2048, 256>>>(tok, emb, gh);
    split_kernel<<<2048, 256>>>(W_in, WinH, WinL, WIN_SZ);
    split_kernel<<<2048, 256>>>(W_out, WoutH, WoutL, WOUT_SZ);
    split_kernel<<<64, 256>>>(head_w, HeadH, HeadL, HEAD_SZ);

    for (int L = 0; L < NL; L++) {
        rmsnorm_kernel<<<TT, 256>>>(gh, norm_w + L * DM, UH, UL);
        hgemm_kernel<<<dim3((DPROJ + HBN_ - 1) / HBN_, TT / HBM_), 256>>>(
            UH, UL, WinH + (size_t)L * DM * DPROJ, WinL + (size_t)L * DM * DPROJ,
            b_in + L * DPROJ, nullptr, gzx, TT, DPROJ, DM);
        conv_dt_kernel<<<TT, 128>>>(gzx, conv_w + L * CONV * KC,
                                    conv_b + L * CONV, dt_bias + L * NH,
                                    A_log + L * NH, gxc, gB, gC, gdt, gdA);
        scan_kernel<<<BB * NH * 4, 128>>>(gxc, gB, gC, gdt, gdA,
                                          D_param + L * NH, gy);
        gate_norm_kernel<<<TT, 256>>>(gy, gzx, gnorm_w + L * DIN, GHp, GLp);
        hgemm_kernel<<<dim3(DM / HBN_, TT / HBM_), 256>>>(
            GHp, GLp, WoutH + (size_t)L * DIN * DM, WoutL + (size_t)L * DIN * DM,
            b_out + L * DM, gh, gh, TT, DM, DIN);
    }

    split_kernel<<<2048, 256>>>(gh, HHp, HLp, U_SZ);
    hgemm_kernel<<<dim3(1, TT / HBM_), 256>>>(
        HHp, HLp, HeadH, HeadL, head_b, nullptr, (float*)d_out, TT, VOCAB, DM);
}